// round 1
// baseline (speedup 1.0000x reference)
#include <cuda_runtime.h>

#define NB 4096
#define N2 8192
#define DD 256
#define INV_TEMP 2.0f

// Scratch (static device globals — no allocation)
__device__ float g_z[(size_t)N2 * DD];        // normalized rows [8192][256]
__device__ float g_partial[16 * N2];          // per-col-chunk row sums of exp(sim)
__device__ float g_loss[N2];                  // per-row loss

// ---------------------------------------------------------------------------
// Kernel 1: L2-normalize rows of [x_i; x_j] into g_z. One warp per row.
// ---------------------------------------------------------------------------
__global__ void k_normalize(const float* __restrict__ xi, const float* __restrict__ xj) {
    int row  = blockIdx.x * 8 + (threadIdx.x >> 5);
    int lane = threadIdx.x & 31;
    const float* src = (row < NB) ? (xi + (size_t)row * DD)
                                  : (xj + (size_t)(row - NB) * DD);
    float4 v0 = *(const float4*)(src + lane * 4);
    float4 v1 = *(const float4*)(src + 128 + lane * 4);
    float s = v0.x*v0.x + v0.y*v0.y + v0.z*v0.z + v0.w*v0.w
            + v1.x*v1.x + v1.y*v1.y + v1.z*v1.z + v1.w*v1.w;
    #pragma unroll
    for (int o = 16; o > 0; o >>= 1) s += __shfl_xor_sync(0xffffffffu, s, o);
    float inv = 1.0f / fmaxf(sqrtf(s), 1e-12f);
    float* dst = g_z + (size_t)row * DD;
    v0.x *= inv; v0.y *= inv; v0.z *= inv; v0.w *= inv;
    v1.x *= inv; v1.y *= inv; v1.z *= inv; v1.w *= inv;
    *(float4*)(dst + lane * 4)       = v0;
    *(float4*)(dst + 128 + lane * 4) = v1;
}

// ---------------------------------------------------------------------------
// Kernel 2: tiled GEMM-like exp-row-sum.
// Block: 256 threads, computes 64 rows x 512 cols of exp(sim), accumulating
// per-row sums. Grid (128 row tiles, 16 col chunks). sim never materialized.
// Smem tiles are k-major ([k][row], pad to 68 floats) so the compute loop
// uses conflict-free LDS.128.
// ---------------------------------------------------------------------------
__global__ __launch_bounds__(256) void k_expsum() {
    __shared__ float As[32][68];
    __shared__ float Bs[32][68];
    __shared__ float red[64][17];

    int tid = threadIdx.x;
    int tx = tid & 15;        // col micro index
    int ty = tid >> 4;        // row micro index
    int r0 = blockIdx.x * 64;

    float rowAcc0 = 0.f, rowAcc1 = 0.f, rowAcc2 = 0.f, rowAcc3 = 0.f;

    for (int ct = 0; ct < 8; ++ct) {
        int c0 = blockIdx.y * 512 + ct * 64;
        float acc[4][4];
        #pragma unroll
        for (int i = 0; i < 4; ++i)
            #pragma unroll
            for (int j = 0; j < 4; ++j) acc[i][j] = 0.f;

        for (int kt = 0; kt < 8; ++kt) {
            int k0 = kt * 32;
            // Load 64x32 tiles of A-rows and B-rows, transposed to k-major.
            #pragma unroll
            for (int L = 0; L < 2; ++L) {
                int f   = tid + L * 256;       // float4 index 0..511
                int row = f >> 3;
                int ks  = (f & 7) * 4;
                float4 v = *(const float4*)&g_z[(size_t)(r0 + row) * DD + k0 + ks];
                As[ks + 0][row] = v.x; As[ks + 1][row] = v.y;
                As[ks + 2][row] = v.z; As[ks + 3][row] = v.w;
                float4 w = *(const float4*)&g_z[(size_t)(c0 + row) * DD + k0 + ks];
                Bs[ks + 0][row] = w.x; Bs[ks + 1][row] = w.y;
                Bs[ks + 2][row] = w.z; Bs[ks + 3][row] = w.w;
            }
            __syncthreads();

            #pragma unroll
            for (int kk = 0; kk < 32; ++kk) {
                float4 a = *(const float4*)&As[kk][ty * 4];
                float4 b = *(const float4*)&Bs[kk][tx * 4];
                acc[0][0] += a.x * b.x; acc[0][1] += a.x * b.y;
                acc[0][2] += a.x * b.z; acc[0][3] += a.x * b.w;
                acc[1][0] += a.y * b.x; acc[1][1] += a.y * b.y;
                acc[1][2] += a.y * b.z; acc[1][3] += a.y * b.w;
                acc[2][0] += a.z * b.x; acc[2][1] += a.z * b.y;
                acc[2][2] += a.z * b.z; acc[2][3] += a.z * b.w;
                acc[3][0] += a.w * b.x; acc[3][1] += a.w * b.y;
                acc[3][2] += a.w * b.z; acc[3][3] += a.w * b.w;
            }
            __syncthreads();
        }

        // Epilogue: exp and row-accumulate (16 MUFU per 4096 FMA — cheap).
        rowAcc0 += __expf(acc[0][0] * INV_TEMP) + __expf(acc[0][1] * INV_TEMP)
                 + __expf(acc[0][2] * INV_TEMP) + __expf(acc[0][3] * INV_TEMP);
        rowAcc1 += __expf(acc[1][0] * INV_TEMP) + __expf(acc[1][1] * INV_TEMP)
                 + __expf(acc[1][2] * INV_TEMP) + __expf(acc[1][3] * INV_TEMP);
        rowAcc2 += __expf(acc[2][0] * INV_TEMP) + __expf(acc[2][1] * INV_TEMP)
                 + __expf(acc[2][2] * INV_TEMP) + __expf(acc[2][3] * INV_TEMP);
        rowAcc3 += __expf(acc[3][0] * INV_TEMP) + __expf(acc[3][1] * INV_TEMP)
                 + __expf(acc[3][2] * INV_TEMP) + __expf(acc[3][3] * INV_TEMP);
    }

    // Reduce the 16 tx partials per row deterministically via smem.
    red[ty * 4 + 0][tx] = rowAcc0;
    red[ty * 4 + 1][tx] = rowAcc1;
    red[ty * 4 + 2][tx] = rowAcc2;
    red[ty * 4 + 3][tx] = rowAcc3;
    __syncthreads();
    if (tid < 64) {
        float s = 0.f;
        #pragma unroll
        for (int t = 0; t < 16; ++t) s += red[tid][t];
        g_partial[blockIdx.y * N2 + r0 + tid] = s;
    }
}

// ---------------------------------------------------------------------------
// Kernel 3: per-row loss. One warp per row: recompute diag & positive-pair
// dot products exactly, combine with the 16 partial exp-sums.
// ---------------------------------------------------------------------------
__global__ void k_rowloss() {
    int row  = blockIdx.x * 8 + (threadIdx.x >> 5);
    int lane = threadIdx.x & 31;
    const float* zr = g_z + (size_t)row * DD;
    int partner = (row < NB) ? row + NB : row - NB;
    const float* zp = g_z + (size_t)partner * DD;

    float ds = 0.f, dp = 0.f;
    #pragma unroll
    for (int c = 0; c < 2; ++c) {
        float4 a = *(const float4*)(zr + c * 128 + lane * 4);
        float4 p = *(const float4*)(zp + c * 128 + lane * 4);
        ds += a.x * a.x + a.y * a.y + a.z * a.z + a.w * a.w;
        dp += a.x * p.x + a.y * p.y + a.z * p.z + a.w * p.w;
    }
    #pragma unroll
    for (int o = 16; o > 0; o >>= 1) {
        ds += __shfl_xor_sync(0xffffffffu, ds, o);
        dp += __shfl_xor_sync(0xffffffffu, dp, o);
    }
    if (lane == 0) {
        float S = 0.f;
        #pragma unroll
        for (int c = 0; c < 16; ++c) S += g_partial[c * N2 + row];
        float ed = __expf(ds * INV_TEMP);   // exp(sim[r,r])
        float ep = __expf(dp * INV_TEMP);   // exp(pos)
        float en = S - ed;                  // sum of off-diagonal exps
        g_loss[row] = -logf(ep / (ep + en));
    }
}

// ---------------------------------------------------------------------------
// Kernel 4: deterministic mean over 8192 row losses.
// ---------------------------------------------------------------------------
__global__ void k_reduce(float* __restrict__ out) {
    __shared__ float sm[256];
    float s = 0.f;
    for (int i = threadIdx.x; i < N2; i += 256) s += g_loss[i];
    sm[threadIdx.x] = s;
    __syncthreads();
    for (int st = 128; st > 0; st >>= 1) {
        if (threadIdx.x < st) sm[threadIdx.x] += sm[threadIdx.x + st];
        __syncthreads();
    }
    if (threadIdx.x == 0) out[0] = sm[0] * (1.0f / (float)N2);
}

extern "C" void kernel_launch(void* const* d_in, const int* in_sizes, int n_in,
                              void* d_out, int out_size) {
    const float* xi = (const float*)d_in[0];
    const float* xj = (const float*)d_in[1];
    float* out = (float*)d_out;

    k_normalize<<<N2 / 8, 256>>>(xi, xj);
    dim3 grid(128, 16);
    k_expsum<<<grid, 256>>>();
    k_rowloss<<<N2 / 8, 256>>>();
    k_reduce<<<1, 256>>>(out);
}

// round 3
// speedup vs baseline: 7.3553x; 7.3553x over previous
#include <cuda_runtime.h>
#include <cuda_bf16.h>
#include <cstdint>

#define NB 4096
#define N2 8192
#define DD 256
#define INV_TEMP 2.0f

#define BM 128
#define BN 128
#define NSTRIPE (N2 / BN)        // 64 column stripes
#define PADK 264                 // bf16 elems per smem row (528B, conflict-free ldmatrix)

// Scratch (static device globals — no allocation)
__device__ float          g_z [(size_t)N2 * DD];     // normalized rows fp32
__device__ __nv_bfloat16  g_zb[(size_t)N2 * DD];     // normalized rows bf16
__device__ float          g_partial[NSTRIPE * N2];   // per-stripe row sums of exp(sim)
__device__ float          g_loss[N2];

__device__ __forceinline__ uint32_t smem_u32(const void* p) {
    return (uint32_t)__cvta_generic_to_shared(p);
}

__device__ __forceinline__ void ldsm_x4(uint32_t addr, uint32_t& r0, uint32_t& r1,
                                        uint32_t& r2, uint32_t& r3) {
    asm volatile("ldmatrix.sync.aligned.m8n8.x4.shared.b16 {%0,%1,%2,%3}, [%4];"
                 : "=r"(r0), "=r"(r1), "=r"(r2), "=r"(r3) : "r"(addr));
}

__device__ __forceinline__ void mma_bf16(float* d, const uint32_t* a, const uint32_t* b) {
    asm volatile(
        "mma.sync.aligned.m16n8k16.row.col.f32.bf16.bf16.f32 "
        "{%0,%1,%2,%3}, {%4,%5,%6,%7}, {%8,%9}, {%0,%1,%2,%3};"
        : "+f"(d[0]), "+f"(d[1]), "+f"(d[2]), "+f"(d[3])
        : "r"(a[0]), "r"(a[1]), "r"(a[2]), "r"(a[3]), "r"(b[0]), "r"(b[1]));
}

// ---------------------------------------------------------------------------
// Kernel 1: L2-normalize rows of [x_i; x_j] -> g_z (fp32) and g_zb (bf16).
// ---------------------------------------------------------------------------
__global__ void k_normalize(const float* __restrict__ xi, const float* __restrict__ xj) {
    int row  = blockIdx.x * 8 + (threadIdx.x >> 5);
    int lane = threadIdx.x & 31;
    const float* src = (row < NB) ? (xi + (size_t)row * DD)
                                  : (xj + (size_t)(row - NB) * DD);
    float4 v0 = *(const float4*)(src + lane * 4);
    float4 v1 = *(const float4*)(src + 128 + lane * 4);
    float s = v0.x*v0.x + v0.y*v0.y + v0.z*v0.z + v0.w*v0.w
            + v1.x*v1.x + v1.y*v1.y + v1.z*v1.z + v1.w*v1.w;
    #pragma unroll
    for (int o = 16; o > 0; o >>= 1) s += __shfl_xor_sync(0xffffffffu, s, o);
    float inv = 1.0f / fmaxf(sqrtf(s), 1e-12f);
    v0.x *= inv; v0.y *= inv; v0.z *= inv; v0.w *= inv;
    v1.x *= inv; v1.y *= inv; v1.z *= inv; v1.w *= inv;
    float* dst = g_z + (size_t)row * DD;
    *(float4*)(dst + lane * 4)       = v0;
    *(float4*)(dst + 128 + lane * 4) = v1;

    __nv_bfloat162 b[4];
    b[0] = __floats2bfloat162_rn(v0.x, v0.y);
    b[1] = __floats2bfloat162_rn(v0.z, v0.w);
    b[2] = __floats2bfloat162_rn(v1.x, v1.y);
    b[3] = __floats2bfloat162_rn(v1.z, v1.w);
    __nv_bfloat16* db = g_zb + (size_t)row * DD;
    *(uint2*)(db + lane * 4)       = make_uint2(*(uint32_t*)&b[0], *(uint32_t*)&b[1]);
    *(uint2*)(db + 128 + lane * 4) = make_uint2(*(uint32_t*)&b[2], *(uint32_t*)&b[3]);
}

// ---------------------------------------------------------------------------
// Kernel 2: HMMA (mma.sync bf16) 128x128 tile + exp row-sum epilogue.
// 8 warps in 4(M) x 2(N); warp tile 32x64; full K=256 resident in smem.
// ---------------------------------------------------------------------------
#define SMEM_BYTES (2 * BM * PADK * 2)

__global__ __launch_bounds__(256, 1) void k_expsum_mma() {
    extern __shared__ __nv_bfloat16 smem[];
    __nv_bfloat16* smA = smem;
    __nv_bfloat16* smB = smem + BM * PADK;

    int tid   = threadIdx.x;
    int lane  = tid & 31;
    int wid   = tid >> 5;
    int warpM = wid >> 1;       // 0..3
    int warpN = wid & 1;        // 0..1
    int r0 = blockIdx.x * BM;
    int c0 = blockIdx.y * BN;

    // Load A (rows r0..r0+127) and B (rows c0..c0+127), k-contiguous, padded.
    #pragma unroll
    for (int i = 0; i < 16; ++i) {
        int idx = tid + i * 256;           // 0..4095
        int row = idx >> 5;                // 0..127
        int c16 = (idx & 31) * 8;          // bf16 col, step 8
        *(uint4*)&smA[row * PADK + c16] = *(const uint4*)&g_zb[(size_t)(r0 + row) * DD + c16];
        *(uint4*)&smB[row * PADK + c16] = *(const uint4*)&g_zb[(size_t)(c0 + row) * DD + c16];
    }
    __syncthreads();

    float acc[2][8][4];
    #pragma unroll
    for (int m = 0; m < 2; ++m)
        #pragma unroll
        for (int q = 0; q < 8; ++q)
            #pragma unroll
            for (int e = 0; e < 4; ++e) acc[m][q][e] = 0.f;

    // Precompute per-thread ldmatrix smem addresses (bytes), advance by 32B/kstep.
    uint32_t aAddr[2], bAddr[4];
    {
        int arow_lane = lane & 15;
        int akh       = lane >> 4;         // 0/1 -> k offset 0/8
        #pragma unroll
        for (int m = 0; m < 2; ++m) {
            int row = warpM * 32 + m * 16 + arow_lane;
            aAddr[m] = smem_u32(&smA[row * PADK + akh * 8]);
        }
        int bn  = (lane & 7) | ((lane >> 4) << 3); // n within 16-group
        int bkh = (lane >> 3) & 1;
        #pragma unroll
        for (int q = 0; q < 4; ++q) {
            int n = warpN * 64 + q * 16 + bn;
            bAddr[q] = smem_u32(&smB[n * PADK + bkh * 8]);
        }
    }

    #pragma unroll
    for (int ks = 0; ks < 16; ++ks) {
        uint32_t a[2][4];
        ldsm_x4(aAddr[0] + ks * 32, a[0][0], a[0][1], a[0][2], a[0][3]);
        ldsm_x4(aAddr[1] + ks * 32, a[1][0], a[1][1], a[1][2], a[1][3]);
        uint32_t b[8][2];
        #pragma unroll
        for (int q = 0; q < 4; ++q)
            ldsm_x4(bAddr[q] + ks * 32, b[2*q][0], b[2*q][1], b[2*q+1][0], b[2*q+1][1]);
        #pragma unroll
        for (int m = 0; m < 2; ++m)
            #pragma unroll
            for (int q = 0; q < 8; ++q)
                mma_bf16(acc[m][q], a[m], b[q]);
    }

    // Epilogue: exp + row sums. Thread owns rows (warpM*32 + m*16 + h*8 + lane/4),
    // cols (warpN*64 + q*8 + (lane%4)*2 + {0,1}).
    float rs[2][2] = {{0.f, 0.f}, {0.f, 0.f}};
    #pragma unroll
    for (int m = 0; m < 2; ++m)
        #pragma unroll
        for (int q = 0; q < 8; ++q) {
            rs[m][0] += __expf(INV_TEMP * acc[m][q][0]) + __expf(INV_TEMP * acc[m][q][1]);
            rs[m][1] += __expf(INV_TEMP * acc[m][q][2]) + __expf(INV_TEMP * acc[m][q][3]);
        }
    #pragma unroll
    for (int m = 0; m < 2; ++m)
        #pragma unroll
        for (int h = 0; h < 2; ++h) {
            rs[m][h] += __shfl_xor_sync(0xffffffffu, rs[m][h], 1);
            rs[m][h] += __shfl_xor_sync(0xffffffffu, rs[m][h], 2);
        }

    __syncthreads();                      // smem tiles dead; reuse for reduction
    float* red = (float*)smem;            // [128][2]
    if ((lane & 3) == 0) {
        #pragma unroll
        for (int m = 0; m < 2; ++m)
            #pragma unroll
            for (int h = 0; h < 2; ++h) {
                int row = warpM * 32 + m * 16 + h * 8 + (lane >> 2);
                red[row * 2 + warpN] = rs[m][h];
            }
    }
    __syncthreads();
    if (tid < BM) {
        float s = red[tid * 2] + red[tid * 2 + 1];
        g_partial[blockIdx.y * N2 + r0 + tid] = s;
    }
}

// ---------------------------------------------------------------------------
// Kernel 3: per-row loss. Exact fp32 diag & positive-pair dots.
// ---------------------------------------------------------------------------
__global__ void k_rowloss() {
    int row  = blockIdx.x * 8 + (threadIdx.x >> 5);
    int lane = threadIdx.x & 31;
    const float* zr = g_z + (size_t)row * DD;
    int partner = (row < NB) ? row + NB : row - NB;
    const float* zp = g_z + (size_t)partner * DD;

    float ds = 0.f, dp = 0.f;
    #pragma unroll
    for (int c = 0; c < 2; ++c) {
        float4 a = *(const float4*)(zr + c * 128 + lane * 4);
        float4 p = *(const float4*)(zp + c * 128 + lane * 4);
        ds += a.x * a.x + a.y * a.y + a.z * a.z + a.w * a.w;
        dp += a.x * p.x + a.y * p.y + a.z * p.z + a.w * p.w;
    }
    #pragma unroll
    for (int o = 16; o > 0; o >>= 1) {
        ds += __shfl_xor_sync(0xffffffffu, ds, o);
        dp += __shfl_xor_sync(0xffffffffu, dp, o);
    }
    if (lane == 0) {
        float S = 0.f;
        #pragma unroll
        for (int c = 0; c < NSTRIPE; ++c) S += g_partial[c * N2 + row];
        float ed = __expf(ds * INV_TEMP);   // exp(sim[r,r]) as the GEMM would see (bf16) ~ exact
        float ep = __expf(dp * INV_TEMP);
        float en = S - ed;
        g_loss[row] = -logf(ep / (ep + en));
    }
}

// ---------------------------------------------------------------------------
// Kernel 4: deterministic mean.
// ---------------------------------------------------------------------------
__global__ void k_reduce(float* __restrict__ out) {
    __shared__ float sm[256];
    float s = 0.f;
    for (int i = threadIdx.x; i < N2; i += 256) s += g_loss[i];
    sm[threadIdx.x] = s;
    __syncthreads();
    for (int st = 128; st > 0; st >>= 1) {
        if (threadIdx.x < st) sm[threadIdx.x] += sm[threadIdx.x + st];
        __syncthreads();
    }
    if (threadIdx.x == 0) out[0] = sm[0] * (1.0f / (float)N2);
}

extern "C" void kernel_launch(void* const* d_in, const int* in_sizes, int n_in,
                              void* d_out, int out_size) {
    const float* xi = (const float*)d_in[0];
    const float* xj = (const float*)d_in[1];
    float* out = (float*)d_out;

    cudaFuncSetAttribute(k_expsum_mma, cudaFuncAttributeMaxDynamicSharedMemorySize, SMEM_BYTES);

    k_normalize<<<N2 / 8, 256>>>(xi, xj);
    dim3 grid(N2 / BM, N2 / BN);           // (64, 64)
    k_expsum_mma<<<grid, 256, SMEM_BYTES>>>();
    k_rowloss<<<N2 / 8, 256>>>();
    k_reduce<<<1, 256>>>(out);
}

// round 4
// speedup vs baseline: 9.1839x; 1.2486x over previous
#include <cuda_runtime.h>
#include <cuda_bf16.h>
#include <cstdint>

#define NB 4096
#define N2 8192
#define DD 256
#define INV_TEMP 2.0f

#define BM 128
#define BN 128
#define BK 64
#define NCHUNK (DD / BK)         // 4 k-chunks
#define NSTRIPE (N2 / BN)        // 64 column stripes
#define PADK 72                  // bf16 elems per smem row in a chunk (144B)

// Scratch (static device globals — no allocation)
__device__ float          g_z [(size_t)N2 * DD];     // normalized rows fp32
__device__ __nv_bfloat16  g_zb[(size_t)N2 * DD];     // normalized rows bf16
__device__ float          g_partial[NSTRIPE * N2];   // per-stripe row sums of exp(sim)
__device__ float          g_loss[N2];

__device__ __forceinline__ uint32_t smem_u32(const void* p) {
    return (uint32_t)__cvta_generic_to_shared(p);
}

__device__ __forceinline__ void ldsm_x4(uint32_t addr, uint32_t& r0, uint32_t& r1,
                                        uint32_t& r2, uint32_t& r3) {
    asm volatile("ldmatrix.sync.aligned.m8n8.x4.shared.b16 {%0,%1,%2,%3}, [%4];"
                 : "=r"(r0), "=r"(r1), "=r"(r2), "=r"(r3) : "r"(addr));
}

__device__ __forceinline__ void mma_bf16(float* d, const uint32_t* a, const uint32_t* b) {
    asm volatile(
        "mma.sync.aligned.m16n8k16.row.col.f32.bf16.bf16.f32 "
        "{%0,%1,%2,%3}, {%4,%5,%6,%7}, {%8,%9}, {%0,%1,%2,%3};"
        : "+f"(d[0]), "+f"(d[1]), "+f"(d[2]), "+f"(d[3])
        : "r"(a[0]), "r"(a[1]), "r"(a[2]), "r"(a[3]), "r"(b[0]), "r"(b[1]));
}

__device__ __forceinline__ void cp_async16(uint32_t smem_addr, const void* gptr) {
    asm volatile("cp.async.cg.shared.global [%0], [%1], 16;"
                 :: "r"(smem_addr), "l"(gptr) : "memory");
}
#define CP_COMMIT() asm volatile("cp.async.commit_group;" ::: "memory")
#define CP_WAIT(n)  asm volatile("cp.async.wait_group %0;" :: "n"(n) : "memory")

// ---------------------------------------------------------------------------
// Kernel 1: L2-normalize rows of [x_i; x_j] -> g_z (fp32) and g_zb (bf16).
// ---------------------------------------------------------------------------
__global__ void k_normalize(const float* __restrict__ xi, const float* __restrict__ xj) {
    int row  = blockIdx.x * 8 + (threadIdx.x >> 5);
    int lane = threadIdx.x & 31;
    const float* src = (row < NB) ? (xi + (size_t)row * DD)
                                  : (xj + (size_t)(row - NB) * DD);
    float4 v0 = *(const float4*)(src + lane * 4);
    float4 v1 = *(const float4*)(src + 128 + lane * 4);
    float s = v0.x*v0.x + v0.y*v0.y + v0.z*v0.z + v0.w*v0.w
            + v1.x*v1.x + v1.y*v1.y + v1.z*v1.z + v1.w*v1.w;
    #pragma unroll
    for (int o = 16; o > 0; o >>= 1) s += __shfl_xor_sync(0xffffffffu, s, o);
    float inv = 1.0f / fmaxf(sqrtf(s), 1e-12f);
    v0.x *= inv; v0.y *= inv; v0.z *= inv; v0.w *= inv;
    v1.x *= inv; v1.y *= inv; v1.z *= inv; v1.w *= inv;
    float* dst = g_z + (size_t)row * DD;
    *(float4*)(dst + lane * 4)       = v0;
    *(float4*)(dst + 128 + lane * 4) = v1;

    __nv_bfloat162 b[4];
    b[0] = __floats2bfloat162_rn(v0.x, v0.y);
    b[1] = __floats2bfloat162_rn(v0.z, v0.w);
    b[2] = __floats2bfloat162_rn(v1.x, v1.y);
    b[3] = __floats2bfloat162_rn(v1.z, v1.w);
    __nv_bfloat16* db = g_zb + (size_t)row * DD;
    *(uint2*)(db + lane * 4)       = make_uint2(*(uint32_t*)&b[0], *(uint32_t*)&b[1]);
    *(uint2*)(db + 128 + lane * 4) = make_uint2(*(uint32_t*)&b[2], *(uint32_t*)&b[3]);
}

// ---------------------------------------------------------------------------
// Kernel 2: HMMA 128x128 tile, K pipelined in 4 chunks of 64 via cp.async.
// 8 warps (4M x 2N), warp tile 32x64. Double-buffered smem, 2 CTAs/SM.
// ---------------------------------------------------------------------------
#define CHUNK_ELEMS (BM * PADK)                 // per A or B buffer (bf16)
#define SMEM_BYTES  (2 * 2 * CHUNK_ELEMS * 2)   // 2 bufs x (A,B) = 73728 B

__global__ __launch_bounds__(256, 2) void k_expsum_mma() {
    extern __shared__ __nv_bfloat16 smem[];
    // layout: buf0 A, buf0 B, buf1 A, buf1 B
    int tid   = threadIdx.x;
    int lane  = tid & 31;
    int wid   = tid >> 5;
    int warpM = wid >> 1;
    int warpN = wid & 1;
    int r0 = blockIdx.x * BM;
    int c0 = blockIdx.y * BN;

    // Per-thread load mapping: 4 uint4 for A + 4 for B per chunk.
    int lrow = tid >> 3;              // 0..31 base row (stride 32)
    int lcol = (tid & 7) * 8;         // bf16 col within chunk
    uint32_t sbase = smem_u32(smem);

    // Issue loads for chunk kc into buffer b.
    auto load_chunk = [&](int kc, int b) {
        uint32_t aoff = sbase + (uint32_t)(b * 2 * CHUNK_ELEMS) * 2;
        uint32_t boff = aoff + (uint32_t)CHUNK_ELEMS * 2;
        const __nv_bfloat16* gA = g_zb + (size_t)r0 * DD + kc * BK;
        const __nv_bfloat16* gB = g_zb + (size_t)c0 * DD + kc * BK;
        #pragma unroll
        for (int i = 0; i < 4; ++i) {
            int row = lrow + i * 32;
            cp_async16(aoff + (uint32_t)(row * PADK + lcol) * 2,
                       gA + (size_t)row * DD + lcol);
            cp_async16(boff + (uint32_t)(row * PADK + lcol) * 2,
                       gB + (size_t)row * DD + lcol);
        }
        CP_COMMIT();
    };

    // Precompute per-thread ldmatrix lane offsets (bytes, within a buffer).
    uint32_t aLane[2], bLane[4];
    {
        int arow_lane = lane & 15;
        int akh       = lane >> 4;
        #pragma unroll
        for (int m = 0; m < 2; ++m) {
            int row = warpM * 32 + m * 16 + arow_lane;
            aLane[m] = (uint32_t)(row * PADK + akh * 8) * 2;
        }
        int bn  = (lane & 7) | ((lane >> 4) << 3);
        int bkh = (lane >> 3) & 1;
        #pragma unroll
        for (int q = 0; q < 4; ++q) {
            int n = warpN * 64 + q * 16 + bn;
            bLane[q] = (uint32_t)(n * PADK + bkh * 8) * 2;
        }
    }

    float acc[2][8][4];
    #pragma unroll
    for (int m = 0; m < 2; ++m)
        #pragma unroll
        for (int q = 0; q < 8; ++q)
            #pragma unroll
            for (int e = 0; e < 4; ++e) acc[m][q][e] = 0.f;

    load_chunk(0, 0);

    #pragma unroll
    for (int kc = 0; kc < NCHUNK; ++kc) {
        if (kc + 1 < NCHUNK) {
            load_chunk(kc + 1, (kc + 1) & 1);
            CP_WAIT(1);
        } else {
            CP_WAIT(0);
        }
        __syncthreads();

        uint32_t abuf = sbase + (uint32_t)((kc & 1) * 2 * CHUNK_ELEMS) * 2;
        uint32_t bbuf = abuf + (uint32_t)CHUNK_ELEMS * 2;

        #pragma unroll
        for (int ks = 0; ks < BK / 16; ++ks) {
            uint32_t a[2][4];
            ldsm_x4(abuf + aLane[0] + ks * 32, a[0][0], a[0][1], a[0][2], a[0][3]);
            ldsm_x4(abuf + aLane[1] + ks * 32, a[1][0], a[1][1], a[1][2], a[1][3]);
            uint32_t b[8][2];
            #pragma unroll
            for (int q = 0; q < 4; ++q)
                ldsm_x4(bbuf + bLane[q] + ks * 32,
                        b[2*q][0], b[2*q][1], b[2*q+1][0], b[2*q+1][1]);
            #pragma unroll
            for (int m = 0; m < 2; ++m)
                #pragma unroll
                for (int q = 0; q < 8; ++q)
                    mma_bf16(acc[m][q], a[m], b[q]);
        }
        __syncthreads();
    }

    // Epilogue: exp + row sums.
    float rs[2][2] = {{0.f, 0.f}, {0.f, 0.f}};
    #pragma unroll
    for (int m = 0; m < 2; ++m)
        #pragma unroll
        for (int q = 0; q < 8; ++q) {
            rs[m][0] += __expf(INV_TEMP * acc[m][q][0]) + __expf(INV_TEMP * acc[m][q][1]);
            rs[m][1] += __expf(INV_TEMP * acc[m][q][2]) + __expf(INV_TEMP * acc[m][q][3]);
        }
    #pragma unroll
    for (int m = 0; m < 2; ++m)
        #pragma unroll
        for (int h = 0; h < 2; ++h) {
            rs[m][h] += __shfl_xor_sync(0xffffffffu, rs[m][h], 1);
            rs[m][h] += __shfl_xor_sync(0xffffffffu, rs[m][h], 2);
        }

    float* red = (float*)smem;            // [128][2], smem tiles dead
    if ((lane & 3) == 0) {
        #pragma unroll
        for (int m = 0; m < 2; ++m)
            #pragma unroll
            for (int h = 0; h < 2; ++h) {
                int row = warpM * 32 + m * 16 + h * 8 + (lane >> 2);
                red[row * 2 + warpN] = rs[m][h];
            }
    }
    __syncthreads();
    if (tid < BM) {
        g_partial[blockIdx.y * N2 + r0 + tid] = red[tid * 2] + red[tid * 2 + 1];
    }
}

// ---------------------------------------------------------------------------
// Kernel 3: per-row loss. Exact fp32 diag & positive-pair dots.
// ---------------------------------------------------------------------------
__global__ void k_rowloss() {
    int row  = blockIdx.x * 8 + (threadIdx.x >> 5);
    int lane = threadIdx.x & 31;
    const float* zr = g_z + (size_t)row * DD;
    int partner = (row < NB) ? row + NB : row - NB;
    const float* zp = g_z + (size_t)partner * DD;

    float ds = 0.f, dp = 0.f;
    #pragma unroll
    for (int c = 0; c < 2; ++c) {
        float4 a = *(const float4*)(zr + c * 128 + lane * 4);
        float4 p = *(const float4*)(zp + c * 128 + lane * 4);
        ds += a.x * a.x + a.y * a.y + a.z * a.z + a.w * a.w;
        dp += a.x * p.x + a.y * p.y + a.z * p.z + a.w * p.w;
    }
    #pragma unroll
    for (int o = 16; o > 0; o >>= 1) {
        ds += __shfl_xor_sync(0xffffffffu, ds, o);
        dp += __shfl_xor_sync(0xffffffffu, dp, o);
    }
    if (lane == 0) {
        float S = 0.f;
        #pragma unroll
        for (int c = 0; c < NSTRIPE; ++c) S += g_partial[c * N2 + row];
        float ed = __expf(ds * INV_TEMP);
        float ep = __expf(dp * INV_TEMP);
        float en = S - ed;
        g_loss[row] = -logf(ep / (ep + en));
    }
}

// ---------------------------------------------------------------------------
// Kernel 4: deterministic mean (1024 threads, float4 loads).
// ---------------------------------------------------------------------------
__global__ void k_reduce(float* __restrict__ out) {
    __shared__ float sm[1024];
    int t = threadIdx.x;
    float4 v0 = *(const float4*)&g_loss[t * 4];
    float4 v1 = *(const float4*)&g_loss[4096 + t * 4];
    float s = v0.x + v0.y + v0.z + v0.w + v1.x + v1.y + v1.z + v1.w;
    sm[t] = s;
    __syncthreads();
    for (int st = 512; st > 0; st >>= 1) {
        if (t < st) sm[t] += sm[t + st];
        __syncthreads();
    }
    if (t == 0) out[0] = sm[0] * (1.0f / (float)N2);
}

extern "C" void kernel_launch(void* const* d_in, const int* in_sizes, int n_in,
                              void* d_out, int out_size) {
    const float* xi = (const float*)d_in[0];
    const float* xj = (const float*)d_in[1];
    float* out = (float*)d_out;

    cudaFuncSetAttribute(k_expsum_mma, cudaFuncAttributeMaxDynamicSharedMemorySize, SMEM_BYTES);

    k_normalize<<<N2 / 8, 256>>>(xi, xj);
    dim3 grid(N2 / BM, N2 / BN);           // (64, 64)
    k_expsum_mma<<<grid, 256, SMEM_BYTES>>>();
    k_rowloss<<<N2 / 8, 256>>>();
    k_reduce<<<1, 1024>>>(out);
}

// round 5
// speedup vs baseline: 14.2624x; 1.5530x over previous
#include <cuda_runtime.h>
#include <cuda_bf16.h>
#include <cstdint>

#define NB 4096
#define N2 8192
#define DD 256
#define INV_TEMP 2.0f

#define BM 128
#define BN 128
#define BK 64
#define NCHUNK (DD / BK)         // 4 k-chunks
#define NSTRIPE (N2 / BN)        // 64 column stripes
#define NTILE 64                 // 64x64 tile grid, upper triangle
#define NTRI (NTILE * (NTILE + 1) / 2)   // 2080
#define PADK 72                  // bf16 elems per smem row in a chunk (144B)

// Scratch (static device globals — no allocation)
__device__ float          g_z [(size_t)N2 * DD];     // normalized rows fp32
__device__ __nv_bfloat16  g_zb[(size_t)N2 * DD];     // normalized rows bf16
__device__ float          g_partial[NSTRIPE * N2];   // per-stripe row sums of exp(sim)
__device__ float          g_loss[N2];
__device__ int            g_sem;                     // last-block counter (stays 0)

__device__ __forceinline__ uint32_t smem_u32(const void* p) {
    return (uint32_t)__cvta_generic_to_shared(p);
}

__device__ __forceinline__ void ldsm_x4(uint32_t addr, uint32_t& r0, uint32_t& r1,
                                        uint32_t& r2, uint32_t& r3) {
    asm volatile("ldmatrix.sync.aligned.m8n8.x4.shared.b16 {%0,%1,%2,%3}, [%4];"
                 : "=r"(r0), "=r"(r1), "=r"(r2), "=r"(r3) : "r"(addr));
}

__device__ __forceinline__ void mma_bf16(float* d, const uint32_t* a, const uint32_t* b) {
    asm volatile(
        "mma.sync.aligned.m16n8k16.row.col.f32.bf16.bf16.f32 "
        "{%0,%1,%2,%3}, {%4,%5,%6,%7}, {%8,%9}, {%0,%1,%2,%3};"
        : "+f"(d[0]), "+f"(d[1]), "+f"(d[2]), "+f"(d[3])
        : "r"(a[0]), "r"(a[1]), "r"(a[2]), "r"(a[3]), "r"(b[0]), "r"(b[1]));
}

__device__ __forceinline__ void cp_async16(uint32_t smem_addr, const void* gptr) {
    asm volatile("cp.async.cg.shared.global [%0], [%1], 16;"
                 :: "r"(smem_addr), "l"(gptr) : "memory");
}
#define CP_COMMIT() asm volatile("cp.async.commit_group;" ::: "memory")
#define CP_WAIT(n)  asm volatile("cp.async.wait_group %0;" :: "n"(n) : "memory")

// ---------------------------------------------------------------------------
// Kernel 1: L2-normalize rows of [x_i; x_j] -> g_z (fp32) and g_zb (bf16).
// ---------------------------------------------------------------------------
__global__ void k_normalize(const float* __restrict__ xi, const float* __restrict__ xj) {
    int row  = blockIdx.x * 8 + (threadIdx.x >> 5);
    int lane = threadIdx.x & 31;
    const float* src = (row < NB) ? (xi + (size_t)row * DD)
                                  : (xj + (size_t)(row - NB) * DD);
    float4 v0 = *(const float4*)(src + lane * 4);
    float4 v1 = *(const float4*)(src + 128 + lane * 4);
    float s = v0.x*v0.x + v0.y*v0.y + v0.z*v0.z + v0.w*v0.w
            + v1.x*v1.x + v1.y*v1.y + v1.z*v1.z + v1.w*v1.w;
    #pragma unroll
    for (int o = 16; o > 0; o >>= 1) s += __shfl_xor_sync(0xffffffffu, s, o);
    float inv = 1.0f / fmaxf(sqrtf(s), 1e-12f);
    v0.x *= inv; v0.y *= inv; v0.z *= inv; v0.w *= inv;
    v1.x *= inv; v1.y *= inv; v1.z *= inv; v1.w *= inv;
    float* dst = g_z + (size_t)row * DD;
    *(float4*)(dst + lane * 4)       = v0;
    *(float4*)(dst + 128 + lane * 4) = v1;

    __nv_bfloat162 b[4];
    b[0] = __floats2bfloat162_rn(v0.x, v0.y);
    b[1] = __floats2bfloat162_rn(v0.z, v0.w);
    b[2] = __floats2bfloat162_rn(v1.x, v1.y);
    b[3] = __floats2bfloat162_rn(v1.z, v1.w);
    __nv_bfloat16* db = g_zb + (size_t)row * DD;
    *(uint2*)(db + lane * 4)       = make_uint2(*(uint32_t*)&b[0], *(uint32_t*)&b[1]);
    *(uint2*)(db + 128 + lane * 4) = make_uint2(*(uint32_t*)&b[2], *(uint32_t*)&b[3]);
}

// ---------------------------------------------------------------------------
// Kernel 2: HMMA 128x128 tile on the UPPER TRIANGLE only. Each off-diagonal
// tile (bi<bj) emits row sums (stripe bj, rows of bi) AND column sums
// (stripe bi, rows of bj) from the same exp values. Diagonal: rows only.
// ---------------------------------------------------------------------------
#define CHUNK_ELEMS (BM * PADK)
#define SMEM_BYTES  (2 * 2 * CHUNK_ELEMS * 2)   // 73728 B

__global__ __launch_bounds__(256, 2) void k_expsum_mma() {
    extern __shared__ __nv_bfloat16 smem[];
    int tid   = threadIdx.x;
    int lane  = tid & 31;
    int wid   = tid >> 5;
    int warpM = wid >> 1;
    int warpN = wid & 1;

    // Triangular decode: blockIdx.x -> (bi, bj), bi <= bj.
    int idx = blockIdx.x;
    int bi = (int)(64.5 - sqrt(64.5 * 64.5 - 2.0 * (double)idx));
    while ((bi + 1) * NTILE - ((bi + 1) * bi) / 2 <= idx) ++bi;
    while (bi * NTILE - (bi * (bi - 1)) / 2 > idx) --bi;
    int bj = bi + (idx - (bi * NTILE - (bi * (bi - 1)) / 2));
    int r0 = bi * BM;
    int c0 = bj * BN;

    int lrow = tid >> 3;
    int lcol = (tid & 7) * 8;
    uint32_t sbase = smem_u32(smem);

    auto load_chunk = [&](int kc, int b) {
        uint32_t aoff = sbase + (uint32_t)(b * 2 * CHUNK_ELEMS) * 2;
        uint32_t boff = aoff + (uint32_t)CHUNK_ELEMS * 2;
        const __nv_bfloat16* gA = g_zb + (size_t)r0 * DD + kc * BK;
        const __nv_bfloat16* gB = g_zb + (size_t)c0 * DD + kc * BK;
        #pragma unroll
        for (int i = 0; i < 4; ++i) {
            int row = lrow + i * 32;
            cp_async16(aoff + (uint32_t)(row * PADK + lcol) * 2,
                       gA + (size_t)row * DD + lcol);
            cp_async16(boff + (uint32_t)(row * PADK + lcol) * 2,
                       gB + (size_t)row * DD + lcol);
        }
        CP_COMMIT();
    };

    uint32_t aLane[2], bLane[4];
    {
        int arow_lane = lane & 15;
        int akh       = lane >> 4;
        #pragma unroll
        for (int m = 0; m < 2; ++m) {
            int row = warpM * 32 + m * 16 + arow_lane;
            aLane[m] = (uint32_t)(row * PADK + akh * 8) * 2;
        }
        int bn  = (lane & 7) | ((lane >> 4) << 3);
        int bkh = (lane >> 3) & 1;
        #pragma unroll
        for (int q = 0; q < 4; ++q) {
            int n = warpN * 64 + q * 16 + bn;
            bLane[q] = (uint32_t)(n * PADK + bkh * 8) * 2;
        }
    }

    float acc[2][8][4];
    #pragma unroll
    for (int m = 0; m < 2; ++m)
        #pragma unroll
        for (int q = 0; q < 8; ++q)
            #pragma unroll
            for (int e = 0; e < 4; ++e) acc[m][q][e] = 0.f;

    load_chunk(0, 0);

    #pragma unroll
    for (int kc = 0; kc < NCHUNK; ++kc) {
        if (kc + 1 < NCHUNK) { load_chunk(kc + 1, (kc + 1) & 1); CP_WAIT(1); }
        else                 { CP_WAIT(0); }
        __syncthreads();

        uint32_t abuf = sbase + (uint32_t)((kc & 1) * 2 * CHUNK_ELEMS) * 2;
        uint32_t bbuf = abuf + (uint32_t)CHUNK_ELEMS * 2;

        #pragma unroll
        for (int ks = 0; ks < BK / 16; ++ks) {
            uint32_t a[2][4];
            ldsm_x4(abuf + aLane[0] + ks * 32, a[0][0], a[0][1], a[0][2], a[0][3]);
            ldsm_x4(abuf + aLane[1] + ks * 32, a[1][0], a[1][1], a[1][2], a[1][3]);
            uint32_t b[8][2];
            #pragma unroll
            for (int q = 0; q < 4; ++q)
                ldsm_x4(bbuf + bLane[q] + ks * 32,
                        b[2*q][0], b[2*q][1], b[2*q+1][0], b[2*q+1][1]);
            #pragma unroll
            for (int m = 0; m < 2; ++m)
                #pragma unroll
                for (int q = 0; q < 8; ++q)
                    mma_bf16(acc[m][q], a[m], b[q]);
        }
        __syncthreads();
    }

    // --- exp in place ---
    #pragma unroll
    for (int m = 0; m < 2; ++m)
        #pragma unroll
        for (int q = 0; q < 8; ++q)
            #pragma unroll
            for (int e = 0; e < 4; ++e)
                acc[m][q][e] = __expf(INV_TEMP * acc[m][q][e]);

    float* rowred = (float*)smem;                 // [128][2]
    float* colred = (float*)smem + 256;           // [128][4]

    // --- row sums (reduce over cols: q, e&1, lane%4) ---
    #pragma unroll
    for (int m = 0; m < 2; ++m) {
        float r0s = 0.f, r1s = 0.f;
        #pragma unroll
        for (int q = 0; q < 8; ++q) {
            r0s += acc[m][q][0] + acc[m][q][1];
            r1s += acc[m][q][2] + acc[m][q][3];
        }
        r0s += __shfl_xor_sync(0xffffffffu, r0s, 1);
        r0s += __shfl_xor_sync(0xffffffffu, r0s, 2);
        r1s += __shfl_xor_sync(0xffffffffu, r1s, 1);
        r1s += __shfl_xor_sync(0xffffffffu, r1s, 2);
        if ((lane & 3) == 0) {
            int row0 = warpM * 32 + m * 16 + (lane >> 2);
            rowred[row0 * 2 + warpN]       = r0s;   // note: accumulate below
            rowred[(row0 + 8) * 2 + warpN] = r1s;
        }
    }
    // rowred written per (row, warpN); both warpN slots distinct -> no clash.

    // --- col sums (reduce over rows: m, e>>1, lane/4, warpM) ---
    if (bi != bj) {
        #pragma unroll
        for (int q = 0; q < 8; ++q) {
            float c0s = 0.f, c1s = 0.f;
            #pragma unroll
            for (int m = 0; m < 2; ++m) {
                c0s += acc[m][q][0] + acc[m][q][2];
                c1s += acc[m][q][1] + acc[m][q][3];
            }
            c0s += __shfl_xor_sync(0xffffffffu, c0s, 4);
            c0s += __shfl_xor_sync(0xffffffffu, c0s, 8);
            c0s += __shfl_xor_sync(0xffffffffu, c0s, 16);
            c1s += __shfl_xor_sync(0xffffffffu, c1s, 4);
            c1s += __shfl_xor_sync(0xffffffffu, c1s, 8);
            c1s += __shfl_xor_sync(0xffffffffu, c1s, 16);
            if (lane < 4) {
                int n = warpN * 64 + q * 8 + lane * 2;
                colred[n * 4 + warpM]       = c0s;
                colred[(n + 1) * 4 + warpM] = c1s;
            }
        }
    }
    __syncthreads();

    if (tid < BM) {
        g_partial[bj * N2 + r0 + tid] = rowred[tid * 2] + rowred[tid * 2 + 1];
    } else if (bi != bj) {
        int n = tid - 128;
        g_partial[bi * N2 + c0 + n] =
            colred[n * 4] + colred[n * 4 + 1] + colred[n * 4 + 2] + colred[n * 4 + 3];
    }
}

// ---------------------------------------------------------------------------
// Kernel 3: per-row loss + fused final mean (last block reduces).
// ---------------------------------------------------------------------------
__global__ void k_rowloss(float* __restrict__ out) {
    __shared__ float sm[256];
    __shared__ int isLast;
    int tid  = threadIdx.x;
    int row  = blockIdx.x * 8 + (tid >> 5);
    int lane = tid & 31;
    const float* zr = g_z + (size_t)row * DD;
    int partner = (row < NB) ? row + NB : row - NB;
    const float* zp = g_z + (size_t)partner * DD;

    float ds = 0.f, dp = 0.f;
    #pragma unroll
    for (int c = 0; c < 2; ++c) {
        float4 a = *(const float4*)(zr + c * 128 + lane * 4);
        float4 p = *(const float4*)(zp + c * 128 + lane * 4);
        ds += a.x * a.x + a.y * a.y + a.z * a.z + a.w * a.w;
        dp += a.x * p.x + a.y * p.y + a.z * p.z + a.w * p.w;
    }
    #pragma unroll
    for (int o = 16; o > 0; o >>= 1) {
        ds += __shfl_xor_sync(0xffffffffu, ds, o);
        dp += __shfl_xor_sync(0xffffffffu, dp, o);
    }
    if (lane == 0) {
        float S = 0.f;
        #pragma unroll
        for (int c = 0; c < NSTRIPE; ++c) S += g_partial[c * N2 + row];
        float ed = __expf(ds * INV_TEMP);
        float ep = __expf(dp * INV_TEMP);
        float en = S - ed;
        g_loss[row] = -logf(ep / (ep + en));
    }
    __threadfence();
    __syncthreads();
    if (tid == 0) {
        int old = atomicAdd(&g_sem, 1);
        isLast = (old == gridDim.x - 1);
    }
    __syncthreads();
    if (isLast) {
        float s = 0.f;
        #pragma unroll
        for (int i = 0; i < 8; ++i) {
            float4 v = *(const float4*)&g_loss[(tid + i * 256) * 4];
            s += v.x + v.y + v.z + v.w;
        }
        sm[tid] = s;
        __syncthreads();
        for (int st = 128; st > 0; st >>= 1) {
            if (tid < st) sm[tid] += sm[tid + st];
            __syncthreads();
        }
        if (tid == 0) { out[0] = sm[0] * (1.0f / (float)N2); g_sem = 0; }
    }
}

extern "C" void kernel_launch(void* const* d_in, const int* in_sizes, int n_in,
                              void* d_out, int out_size) {
    const float* xi = (const float*)d_in[0];
    const float* xj = (const float*)d_in[1];
    float* out = (float*)d_out;

    cudaFuncSetAttribute(k_expsum_mma, cudaFuncAttributeMaxDynamicSharedMemorySize, SMEM_BYTES);

    k_normalize<<<N2 / 8, 256>>>(xi, xj);
    k_expsum_mma<<<NTRI, 256, SMEM_BYTES>>>();
    k_rowloss<<<N2 / 8, 256>>>(out);
}

// round 7
// speedup vs baseline: 14.9206x; 1.0461x over previous
#include <cuda_runtime.h>
#include <cuda_bf16.h>
#include <cstdint>

#define NB 4096
#define N2 8192
#define DD 256
#define INV_TEMP 2.0f

#define BM 128
#define BN 128
#define BK 64
#define NCHUNK (DD / BK)         // 4 k-chunks
#define NSTRIPE (N2 / BN)        // 64 column stripes
#define NTILE 64
#define NTRI (NTILE * (NTILE + 1) / 2)   // 2080
#define PADK 72                  // bf16 elems per smem row (144B)

// Scratch (static device globals — no allocation)
__device__ __nv_bfloat16  g_zb[(size_t)N2 * DD];     // normalized rows bf16
__device__ float          g_partial[NSTRIPE * N2];   // per-stripe row sums of exp(sim)
__device__ float          g_loss[N2];
__device__ int            g_sem;                     // last-block counter (stays 0)

__device__ __forceinline__ uint32_t smem_u32(const void* p) {
    return (uint32_t)__cvta_generic_to_shared(p);
}

__device__ __forceinline__ void ldsm_x4(uint32_t addr, uint32_t& r0, uint32_t& r1,
                                        uint32_t& r2, uint32_t& r3) {
    asm volatile("ldmatrix.sync.aligned.m8n8.x4.shared.b16 {%0,%1,%2,%3}, [%4];"
                 : "=r"(r0), "=r"(r1), "=r"(r2), "=r"(r3) : "r"(addr));
}

__device__ __forceinline__ void mma_bf16(float* d, const uint32_t* a, const uint32_t* b) {
    asm volatile(
        "mma.sync.aligned.m16n8k16.row.col.f32.bf16.bf16.f32 "
        "{%0,%1,%2,%3}, {%4,%5,%6,%7}, {%8,%9}, {%0,%1,%2,%3};"
        : "+f"(d[0]), "+f"(d[1]), "+f"(d[2]), "+f"(d[3])
        : "r"(a[0]), "r"(a[1]), "r"(a[2]), "r"(a[3]), "r"(b[0]), "r"(b[1]));
}

__device__ __forceinline__ void cp_async16(uint32_t smem_addr, const void* gptr) {
    asm volatile("cp.async.cg.shared.global [%0], [%1], 16;"
                 :: "r"(smem_addr), "l"(gptr) : "memory");
}
#define CP_COMMIT() asm volatile("cp.async.commit_group;" ::: "memory")
#define CP_WAIT(n)  asm volatile("cp.async.wait_group %0;" :: "n"(n) : "memory")

// ---------------------------------------------------------------------------
// Kernel 1: L2-normalize rows of [x_i; x_j] -> g_zb (bf16 only).
// ---------------------------------------------------------------------------
__global__ void k_normalize(const float* __restrict__ xi, const float* __restrict__ xj) {
    int row  = blockIdx.x * 8 + (threadIdx.x >> 5);
    int lane = threadIdx.x & 31;
    const float* src = (row < NB) ? (xi + (size_t)row * DD)
                                  : (xj + (size_t)(row - NB) * DD);
    float4 v0 = *(const float4*)(src + lane * 4);
    float4 v1 = *(const float4*)(src + 128 + lane * 4);
    float s = v0.x*v0.x + v0.y*v0.y + v0.z*v0.z + v0.w*v0.w
            + v1.x*v1.x + v1.y*v1.y + v1.z*v1.z + v1.w*v1.w;
    #pragma unroll
    for (int o = 16; o > 0; o >>= 1) s += __shfl_xor_sync(0xffffffffu, s, o);
    float inv = 1.0f / fmaxf(sqrtf(s), 1e-12f);
    v0.x *= inv; v0.y *= inv; v0.z *= inv; v0.w *= inv;
    v1.x *= inv; v1.y *= inv; v1.z *= inv; v1.w *= inv;

    __nv_bfloat162 b[4];
    b[0] = __floats2bfloat162_rn(v0.x, v0.y);
    b[1] = __floats2bfloat162_rn(v0.z, v0.w);
    b[2] = __floats2bfloat162_rn(v1.x, v1.y);
    b[3] = __floats2bfloat162_rn(v1.z, v1.w);
    __nv_bfloat16* db = g_zb + (size_t)row * DD;
    *(uint2*)(db + lane * 4)       = make_uint2(*(uint32_t*)&b[0], *(uint32_t*)&b[1]);
    *(uint2*)(db + 128 + lane * 4) = make_uint2(*(uint32_t*)&b[2], *(uint32_t*)&b[3]);
}

// ---------------------------------------------------------------------------
// Kernel 2: HMMA 128x128 tile, upper triangle, 4 warps x (64x64) warp tiles.
// Off-diagonal tiles emit row AND column exp-sums; diagonal: rows only.
// ---------------------------------------------------------------------------
#define CHUNK_ELEMS (BM * PADK)
#define SMEM_BYTES  (2 * 2 * CHUNK_ELEMS * 2)   // 73728 B

__global__ __launch_bounds__(128, 2) void k_expsum_mma() {
    extern __shared__ __nv_bfloat16 smem[];
    int tid   = threadIdx.x;
    int lane  = tid & 31;
    int wid   = tid >> 5;          // 0..3
    int warpM = wid >> 1;          // 0..1
    int warpN = wid & 1;           // 0..1

    // Triangular decode: blockIdx.x -> (bi, bj), bi <= bj.
    int idx = blockIdx.x;
    int bi = (int)(64.5f - sqrtf(64.5f * 64.5f - 2.0f * (float)idx));
    while ((bi + 1) * NTILE - ((bi + 1) * bi) / 2 <= idx) ++bi;
    while (bi * NTILE - (bi * (bi - 1)) / 2 > idx) --bi;
    int bj = bi + (idx - (bi * NTILE - (bi * (bi - 1)) / 2));
    int r0 = bi * BM;
    int c0 = bj * BN;

    int lrow = tid >> 3;              // 0..15
    int lcol = (tid & 7) * 8;
    uint32_t sbase = smem_u32(smem);

    auto load_chunk = [&](int kc, int b) {
        uint32_t aoff = sbase + (uint32_t)(b * 2 * CHUNK_ELEMS) * 2;
        uint32_t boff = aoff + (uint32_t)CHUNK_ELEMS * 2;
        const __nv_bfloat16* gA = g_zb + (size_t)r0 * DD + kc * BK;
        const __nv_bfloat16* gB = g_zb + (size_t)c0 * DD + kc * BK;
        #pragma unroll
        for (int i = 0; i < 8; ++i) {
            int row = lrow + i * 16;
            cp_async16(aoff + (uint32_t)(row * PADK + lcol) * 2,
                       gA + (size_t)row * DD + lcol);
            cp_async16(boff + (uint32_t)(row * PADK + lcol) * 2,
                       gB + (size_t)row * DD + lcol);
        }
        CP_COMMIT();
    };

    // ldmatrix lane offsets (bytes within buffer): A m=0..3, B q=0..3 (x4 pairs)
    uint32_t aLane[4], bLane[4];
    {
        int arow_lane = lane & 15;
        int akh       = lane >> 4;
        #pragma unroll
        for (int m = 0; m < 4; ++m) {
            int row = warpM * 64 + m * 16 + arow_lane;
            aLane[m] = (uint32_t)(row * PADK + akh * 8) * 2;
        }
        int bn  = (lane & 7) | ((lane >> 4) << 3);
        int bkh = (lane >> 3) & 1;
        #pragma unroll
        for (int q = 0; q < 4; ++q) {
            int n = warpN * 64 + q * 16 + bn;
            bLane[q] = (uint32_t)(n * PADK + bkh * 8) * 2;
        }
    }

    float acc[4][8][4];
    #pragma unroll
    for (int m = 0; m < 4; ++m)
        #pragma unroll
        for (int q = 0; q < 8; ++q)
            #pragma unroll
            for (int e = 0; e < 4; ++e) acc[m][q][e] = 0.f;

    load_chunk(0, 0);

    #pragma unroll
    for (int kc = 0; kc < NCHUNK; ++kc) {
        if (kc + 1 < NCHUNK) { load_chunk(kc + 1, (kc + 1) & 1); CP_WAIT(1); }
        else                 { CP_WAIT(0); }
        __syncthreads();

        uint32_t abuf = sbase + (uint32_t)((kc & 1) * 2 * CHUNK_ELEMS) * 2;
        uint32_t bbuf = abuf + (uint32_t)CHUNK_ELEMS * 2;

        #pragma unroll
        for (int ks = 0; ks < BK / 16; ++ks) {
            uint32_t a[4][4];
            #pragma unroll
            for (int m = 0; m < 4; ++m)
                ldsm_x4(abuf + aLane[m] + ks * 32, a[m][0], a[m][1], a[m][2], a[m][3]);
            uint32_t b[8][2];
            #pragma unroll
            for (int q = 0; q < 4; ++q)
                ldsm_x4(bbuf + bLane[q] + ks * 32,
                        b[2*q][0], b[2*q][1], b[2*q+1][0], b[2*q+1][1]);
            #pragma unroll
            for (int m = 0; m < 4; ++m)
                #pragma unroll
                for (int q = 0; q < 8; ++q)
                    mma_bf16(acc[m][q], a[m], b[q]);
        }
        __syncthreads();
    }

    // --- exp in place ---
    #pragma unroll
    for (int m = 0; m < 4; ++m)
        #pragma unroll
        for (int q = 0; q < 8; ++q)
            #pragma unroll
            for (int e = 0; e < 4; ++e)
                acc[m][q][e] = __expf(INV_TEMP * acc[m][q][e]);

    float* rowred = (float*)smem;                 // [128][2] by warpN
    float* colred = (float*)smem + 256;           // [128][2] by warpM

    // --- row sums (reduce over q, e-pairs, lane%4) ---
    #pragma unroll
    for (int m = 0; m < 4; ++m) {
        float r0s = 0.f, r1s = 0.f;
        #pragma unroll
        for (int q = 0; q < 8; ++q) {
            r0s += acc[m][q][0] + acc[m][q][1];
            r1s += acc[m][q][2] + acc[m][q][3];
        }
        r0s += __shfl_xor_sync(0xffffffffu, r0s, 1);
        r0s += __shfl_xor_sync(0xffffffffu, r0s, 2);
        r1s += __shfl_xor_sync(0xffffffffu, r1s, 1);
        r1s += __shfl_xor_sync(0xffffffffu, r1s, 2);
        if ((lane & 3) == 0) {
            int row = warpM * 64 + m * 16 + (lane >> 2);
            rowred[row * 2 + warpN]       = r0s;
            rowred[(row + 8) * 2 + warpN] = r1s;
        }
    }

    // --- col sums (reduce over m, e rows, lane/4) ---
    if (bi != bj) {
        #pragma unroll
        for (int q = 0; q < 8; ++q) {
            float c0s = 0.f, c1s = 0.f;
            #pragma unroll
            for (int m = 0; m < 4; ++m) {
                c0s += acc[m][q][0] + acc[m][q][2];
                c1s += acc[m][q][1] + acc[m][q][3];
            }
            c0s += __shfl_xor_sync(0xffffffffu, c0s, 4);
            c0s += __shfl_xor_sync(0xffffffffu, c0s, 8);
            c0s += __shfl_xor_sync(0xffffffffu, c0s, 16);
            c1s += __shfl_xor_sync(0xffffffffu, c1s, 4);
            c1s += __shfl_xor_sync(0xffffffffu, c1s, 8);
            c1s += __shfl_xor_sync(0xffffffffu, c1s, 16);
            if (lane < 4) {
                int n = warpN * 64 + q * 8 + lane * 2;
                colred[n * 2 + warpM]       = c0s;
                colred[(n + 1) * 2 + warpM] = c1s;
            }
        }
    }
    __syncthreads();

    g_partial[bj * N2 + r0 + tid] = rowred[tid * 2] + rowred[tid * 2 + 1];
    if (bi != bj)
        g_partial[bi * N2 + c0 + tid] = colred[tid * 2] + colred[tid * 2 + 1];
}

// ---------------------------------------------------------------------------
// Kernel 3: per-row loss + fused final mean. Dots recomputed in fp32 from
// the SAME bf16 values the GEMM consumed. One 16B load per lane (aligned).
// ---------------------------------------------------------------------------
__global__ void k_rowloss(float* __restrict__ out) {
    __shared__ float sm[256];
    __shared__ int isLast;
    int tid  = threadIdx.x;
    int row  = blockIdx.x * 8 + (tid >> 5);
    int lane = tid & 31;
    const __nv_bfloat16* zr = g_zb + (size_t)row * DD;
    int partner = (row < NB) ? row + NB : row - NB;
    const __nv_bfloat16* zp = g_zb + (size_t)partner * DD;

    float ds = 0.f, dp = 0.f;
    {
        uint4 av = *(const uint4*)(zr + lane * 8);   // 8 bf16, 16B aligned
        uint4 pv = *(const uint4*)(zp + lane * 8);
        const __nv_bfloat162* ah = (const __nv_bfloat162*)&av;
        const __nv_bfloat162* ph = (const __nv_bfloat162*)&pv;
        #pragma unroll
        for (int h = 0; h < 4; ++h) {
            float2 a2 = __bfloat1622float2(ah[h]);
            float2 p2 = __bfloat1622float2(ph[h]);
            ds += a2.x * a2.x + a2.y * a2.y;
            dp += a2.x * p2.x + a2.y * p2.y;
        }
    }
    #pragma unroll
    for (int o = 16; o > 0; o >>= 1) {
        ds += __shfl_xor_sync(0xffffffffu, ds, o);
        dp += __shfl_xor_sync(0xffffffffu, dp, o);
    }
    if (lane == 0) {
        float S = 0.f;
        #pragma unroll
        for (int c = 0; c < NSTRIPE; ++c) S += g_partial[c * N2 + row];
        float ed = __expf(ds * INV_TEMP);
        float ep = __expf(dp * INV_TEMP);
        float en = S - ed;
        g_loss[row] = -logf(ep / (ep + en));
    }
    __threadfence();
    __syncthreads();
    if (tid == 0) {
        int old = atomicAdd(&g_sem, 1);
        isLast = (old == gridDim.x - 1);
    }
    __syncthreads();
    if (isLast) {
        float s = 0.f;
        #pragma unroll
        for (int i = 0; i < 8; ++i) {
            float4 v = *(const float4*)&g_loss[(tid + i * 256) * 4];
            s += v.x + v.y + v.z + v.w;
        }
        sm[tid] = s;
        __syncthreads();
        for (int st = 128; st > 0; st >>= 1) {
            if (tid < st) sm[tid] += sm[tid + st];
            __syncthreads();
        }
        if (tid == 0) { out[0] = sm[0] * (1.0f / (float)N2); g_sem = 0; }
    }
}

extern "C" void kernel_launch(void* const* d_in, const int* in_sizes, int n_in,
                              void* d_out, int out_size) {
    const float* xi = (const float*)d_in[0];
    const float* xj = (const float*)d_in[1];
    float* out = (float*)d_out;

    cudaFuncSetAttribute(k_expsum_mma, cudaFuncAttributeMaxDynamicSharedMemorySize, SMEM_BYTES);

    k_normalize<<<N2 / 8, 256>>>(xi, xj);
    k_expsum_mma<<<NTRI, 128, SMEM_BYTES>>>();
    k_rowloss<<<N2 / 8, 256>>>(out);
}